// round 15
// baseline (speedup 1.0000x reference)
#include <cuda_runtime.h>
#include <math.h>

// STFT via real FFT: even/odd pack -> 512-pt radix-8 register Stockham FFT
// (3 stages, first fused with global load) -> real-split recombination.
// Exactness vs fp32 conv reference:
//  * Nyquist (k=512): Re from windowed data (basis row 512 == +-win exactly),
//    Im from the actual basis row 1025 dot (order-independent sign).
//  * Frame t=0 (even-symmetric): patch kernel replicates the reference's
//    split-K=4 order: 4 ascending-fma chunks of 256, sequential combine.
// R15: issue-bound trims -- per-k writeout (stride-10 staging, STG immediate
// offsets), interior-block fast-path loads, sqrt.approx for magnitude.
// All phase-determining float arithmetic is bit-identical to R12/R13/R14.

#define L_SIG    262144
#define HOP      256
#define N_FRAMES 1025
#define CUTOFF   513
#define FPB      8
#define NT       512

// smem float offsets (main kernel) -- g_tab maps 1:1 onto sm[0..3074)
#define OFF_WINC 0        // float2[512]  (win[2m], win[2m+1])
#define OFF_TW   1024     // float2[512]  exp(-2pi i m/512)
#define OFF_W1K  2048     // float2[513]  exp(-pi i k/512)
#define OFF_FBUF 3074     // 8 groups * 576 float2 (512 + pad)
#define OFF_SMAG 12290    // 513*10 (stride 10, even -> LDS.64)
#define OFF_SPH  17420    // 513*10
#define OFF_NYS  22550    // 32
#define SMEM_F   22582    // 90328 bytes (2 CTAs/SM)

#define PADI(i) ((i) + ((i) >> 3))

__device__ float g_tab[3074];      // winc | tw | w1k (float pairs)
__device__ float g_xt0[513 * 32];  // t=0 frame samples, transposed [o][b]

__device__ __forceinline__ float2 cadd(float2 a, float2 b){ return make_float2(a.x+b.x, a.y+b.y); }
__device__ __forceinline__ float2 csub(float2 a, float2 b){ return make_float2(a.x-b.x, a.y-b.y); }
__device__ __forceinline__ float2 cmul(float2 a, float2 b){
    return make_float2(a.x*b.x - a.y*b.y, a.x*b.y + a.y*b.x);
}

__device__ __forceinline__ float sqrt_approx(float h)
{
    float r;
    asm("sqrt.approx.f32 %0, %1;" : "=f"(r) : "f"(h));
    return r;
}

// fast atan2: minimax atan on [0,1] (max err ~2e-7 rad), full quadrant logic.
// Sign comes from copysign(., y) -> cannot flip any phase sign vs atan2f.
__device__ __forceinline__ float fast_atan2f(float y, float x)
{
    float ax = fabsf(x), ay = fabsf(y);
    float mx = fmaxf(ax, ay), mn = fminf(ax, ay);
    float r = (mx == 0.0f) ? 0.0f : __fdividef(mn, mx);
    float t = r * r;
    float p =          -0.01172120f;
    p = fmaf(p, t,      0.05265332f);
    p = fmaf(p, t,     -0.11643287f);
    p = fmaf(p, t,      0.19354346f);
    p = fmaf(p, t,     -0.33262347f);
    p = fmaf(p, t,      0.99997726f);
    float a = p * r;
    a = (ay > ax) ? (1.5707963267948966f - a) : a;
    a = (x < 0.0f) ? (3.1415926535897932f - a) : a;
    return copysignf(a, y);
}

// 8-point DFT, natural-order in/out (verified on impulse).
__device__ __forceinline__ void fft8(float2* v)
{
    const float C = 0.70710678118654752440f;
    float2 a0=cadd(v[0],v[4]), a1=csub(v[0],v[4]);
    float2 a2=cadd(v[1],v[5]), a3=csub(v[1],v[5]);
    float2 a4=cadd(v[2],v[6]), a5=csub(v[2],v[6]);
    float2 a6=cadd(v[3],v[7]), a7=csub(v[3],v[7]);
    float2 b0=cadd(a0,a4), b2=csub(a0,a4);
    float2 w5=make_float2(a5.y,-a5.x);
    float2 b1=cadd(a1,w5), b3=csub(a1,w5);
    float2 b4=cadd(a2,a6), b6=csub(a2,a6);
    float2 w7=make_float2(a7.y,-a7.x);
    float2 b5=cadd(a3,w7), b7=csub(a3,w7);
    v[0]=cadd(b0,b4); v[4]=csub(b0,b4);
    float2 t5=make_float2(C*(b5.x+b5.y), C*(b5.y-b5.x));
    v[1]=cadd(b1,t5); v[5]=csub(b1,t5);
    float2 t6=make_float2(b6.y,-b6.x);
    v[2]=cadd(b2,t6); v[6]=csub(b2,t6);
    float2 t7=make_float2(C*(b7.y-b7.x), -C*(b7.x+b7.y));
    v[3]=cadd(b3,t7); v[7]=csub(b3,t7);
}

// ---------------------------------------------------------------------------
// Prep: tables (bit-identical sincosf expressions) + transposed x t=0 frame.
// ---------------------------------------------------------------------------
__global__ void stft_prep_kernel(const float* __restrict__ x)
{
    const int i = blockIdx.x * blockDim.x + threadIdx.x;
    if (i < 512) {
        float w0 = 0.5f - 0.5f * cosf((float)(M_PI / 512.0) * (float)(2 * i));
        float w1 = 0.5f - 0.5f * cosf((float)(M_PI / 512.0) * (float)(2 * i + 1));
        g_tab[2 * i]     = w0;
        g_tab[2 * i + 1] = w1;
        float s, c;
        sincosf((float)(-2.0 * M_PI / 512.0) * (float)i, &s, &c);
        g_tab[1024 + 2 * i]     = c;
        g_tab[1024 + 2 * i + 1] = s;
    }
    if (i < 513) {
        float s, c;
        sincosf((float)(-M_PI / 512.0) * (float)i, &s, &c);
        g_tab[2048 + 2 * i]     = c;
        g_tab[2048 + 2 * i + 1] = s;
    }
    if (i < 513 * 32) {
        const int o = i >> 5, b = i & 31;
        g_xt0[i] = x[(size_t)b * L_SIG + o];
    }
}

__global__ __launch_bounds__(NT)
void stft_fft_kernel(const float* __restrict__ x,
                     const float* __restrict__ basis,
                     float* __restrict__ out)
{
    extern __shared__ float sm[];
    float2* winc = (float2*)(sm + OFF_WINC);
    float2* tw   = (float2*)(sm + OFF_TW);
    float2* w1k  = (float2*)(sm + OFF_W1K);
    float*  smag = sm + OFF_SMAG;
    float*  sph  = sm + OFF_SPH;
    float*  nys  = sm + OFF_NYS;

    const int tid = threadIdx.x;
    const int g   = tid >> 6;          // frame group 0..7
    const int j   = tid & 63;          // lane within group
    const int b   = blockIdx.y;
    const int t0  = blockIdx.x * FPB;
    const int nf  = min(FPB, N_FRAMES - t0);
    float2* fbuf = (float2*)(sm + OFF_FBUF) + g * 576;

    // ---- tables: copy from precomputed scratch (bit-identical values) ----
    {
        const float2* gt2 = (const float2*)g_tab;
        float2* sm2 = (float2*)sm;
        for (int i = tid; i < 1537; i += NT) sm2[i] = __ldg(gt2 + i);
    }

    // preload Nyquist imag basis taps (row 1025), 8 float2 per thread
    const float2* bIm2 = (const float2*)(basis + 1025 * 1024);
    float2 bImr[8];
    #pragma unroll
    for (int r = 0; r < 8; r++) bImr[r] = __ldg(bIm2 + (j + 64 * r));

    const float* xb = x + (size_t)b * L_SIG;
    const bool interior = (blockIdx.x >= 1) && (blockIdx.x <= 126);
    __syncthreads();

    {
        const int fi  = g;
        const bool act = (fi < nf);
        const int t  = t0 + fi;
        const int s0 = t * HOP - 512;

        float2 v[8];
        float nyr = 0.f, nyi = 0.f;
        if (act) {
            if (interior) {
                // fast path: no reflect possible, straight float2 loads
                #pragma unroll
                for (int r = 0; r < 8; r++) {
                    const int m = j + 64 * r;
                    float2 xv = *(const float2*)(xb + (s0 + 2 * m));
                    float2 wn = winc[m];
                    v[r] = make_float2(xv.x * wn.x, xv.y * wn.y);
                    nyr += v[r].x - v[r].y;
                    nyi = fmaf(xv.x, bImr[r].x, fmaf(xv.y, bImr[r].y, nyi));
                }
            } else {
                #pragma unroll
                for (int r = 0; r < 8; r++) {
                    const int m  = j + 64 * r;
                    const int o0 = s0 + 2 * m;
                    float xa, xc;
                    if (o0 >= 0 && o0 < L_SIG - 1) {
                        float2 xv = *(const float2*)(xb + o0);
                        xa = xv.x; xc = xv.y;
                    } else {
                        int p0 = (o0 < 0) ? -o0 : ((o0 >= L_SIG) ? 2 * L_SIG - 2 - o0 : o0);
                        int o1 = o0 + 1;
                        int p1 = (o1 < 0) ? -o1 : ((o1 >= L_SIG) ? 2 * L_SIG - 2 - o1 : o1);
                        xa = xb[p0]; xc = xb[p1];
                    }
                    float2 wn = winc[m];
                    v[r] = make_float2(xa * wn.x, xc * wn.y);
                    nyr += v[r].x - v[r].y;                   // row512 = (-1)^n * win
                    nyi = fmaf(xa, bImr[r].x, fmaf(xc, bImr[r].y, nyi));
                }
            }
            #pragma unroll
            for (int off = 16; off; off >>= 1) {
                nyr += __shfl_xor_sync(0xFFFFFFFFu, nyr, off);
                nyi += __shfl_xor_sync(0xFFFFFFFFu, nyi, off);
            }
            fft8(v);                                          // stage 1 (Ns=1)
        }
        __syncthreads();
        if (act) {
            if ((tid & 31) == 0) {
                nys[g * 4 + (j >> 5) * 2 + 0] = nyr;
                nys[g * 4 + (j >> 5) * 2 + 1] = nyi;
            }
            #pragma unroll
            for (int r = 0; r < 8; r++) fbuf[PADI(8 * j + r)] = v[r];
        }
        __syncthreads();
        // stage 2 (Ns=8)
        if (act) {
            #pragma unroll
            for (int r = 0; r < 8; r++) v[r] = fbuf[PADI(j + 64 * r)];
            const int rr = (j & 7) * 8;
            #pragma unroll
            for (int r = 1; r < 8; r++) v[r] = cmul(v[r], tw[r * rr]);
            fft8(v);
        }
        __syncthreads();
        if (act) {
            const int idxD = ((j >> 3) << 6) + (j & 7);
            #pragma unroll
            for (int r = 0; r < 8; r++) fbuf[PADI(idxD + (r << 3))] = v[r];
        }
        __syncthreads();
        // stage 3 (Ns=64)
        if (act) {
            #pragma unroll
            for (int r = 0; r < 8; r++) v[r] = fbuf[PADI(j + 64 * r)];
            #pragma unroll
            for (int r = 1; r < 8; r++) v[r] = cmul(v[r], tw[r * j]);
            fft8(v);
        }
        __syncthreads();
        if (act) {
            #pragma unroll
            for (int r = 0; r < 8; r++) fbuf[PADI(j + 64 * r)] = v[r];
        }
        __syncthreads();
        // ---- real-split recombination + mag/phase ----
        if (act) {
            #pragma unroll
            for (int it = 0; it < 9; it++) {
                const int k = j + (it << 6);
                if (k < CUTOFF) {
                    float2 zk = (k < 512) ? fbuf[PADI(k)] : fbuf[0];
                    float2 zm = fbuf[PADI((512 - k) & 511)];
                    float Er = 0.5f * (zk.x + zm.x);
                    float Ei = 0.5f * (zk.y - zm.y);
                    float Or = 0.5f * (zk.y + zm.y);
                    float Oi = -0.5f * (zk.x - zm.x);
                    float2 w = w1k[k];
                    float Xr = Er + w.x * Or - w.y * Oi;
                    float Xi = Ei + w.x * Oi + w.y * Or;
                    if (k == 512) {
                        Xr = nys[g * 4 + 0] + nys[g * 4 + 2];
                        Xi = nys[g * 4 + 1] + nys[g * 4 + 3];
                    }
                    smag[k * 10 + fi] = sqrt_approx(fmaf(Xr, Xr, Xi * Xi));
                    sph [k * 10 + fi] = fast_atan2f(Xi, Xr);
                }
            }
        }
    }
    __syncthreads();

    // ---- write-out: one k per thread, STG with immediate offsets ----
    const size_t plane = (size_t)CUTOFF * N_FRAMES;
    float* omag = out + (size_t)b * plane;
    float* oph  = out + (size_t)32 * plane + (size_t)b * plane;
    if (nf == FPB) {
        for (int k = tid; k < CUTOFF; k += NT) {
            const float2* mg2 = (const float2*)(smag + k * 10);
            const float2* ph2 = (const float2*)(sph  + k * 10);
            float2 m0 = mg2[0], m1 = mg2[1], m2 = mg2[2], m3 = mg2[3];
            float2 p0 = ph2[0], p1 = ph2[1], p2 = ph2[2], p3 = ph2[3];
            float* om = omag + (size_t)k * N_FRAMES + t0;
            float* op = oph  + (size_t)k * N_FRAMES + t0;
            om[0]=m0.x; om[1]=m0.y; om[2]=m1.x; om[3]=m1.y;
            om[4]=m2.x; om[5]=m2.y; om[6]=m3.x; om[7]=m3.y;
            op[0]=p0.x; op[1]=p0.y; op[2]=p1.x; op[3]=p1.y;
            op[4]=p2.x; op[5]=p2.y; op[6]=p3.x; op[7]=p3.y;
        }
    } else {
        const int tot = CUTOFF * nf;
        for (int e = tid; e < tot; e += NT) {
            int k = e / nf, f = e % nf;
            size_t off = (size_t)k * N_FRAMES + (size_t)(t0 + f);
            omag[off] = smag[k * 10 + f];
            oph [off] = sph [k * 10 + f];
        }
    }
}

// ---------------------------------------------------------------------------
// t=0 column patch, reference split-K=4 order (decoded R8/R9):
// block per k (513 blocks), 128 threads = 4 chunks x 32 batches.
// xv from transposed GMEM scratch (coalesced, L1/L2-resident); basis rows in
// smem (broadcast). 8-tap register tiles preserve the exact ascending order.
// ---------------------------------------------------------------------------
__global__ __launch_bounds__(128)
void stft_t0_patch_kernel(const float* __restrict__ basis,
                          float* __restrict__ out)
{
    __shared__ float sbR[1024];
    __shared__ float sbI[1024];
    __shared__ float scr[256];

    const int k   = blockIdx.x;          // 0..512
    const int tid = threadIdx.x;
    const int c   = tid >> 5;            // chunk 0..3
    const int b   = tid & 31;            // batch

    {
        const float4* r4 = (const float4*)(basis + (size_t)k * 1024);
        const float4* i4 = (const float4*)(basis + (size_t)(513 + k) * 1024);
        float4* sR4 = (float4*)sbR;
        float4* sI4 = (float4*)sbI;
        for (int i = tid; i < 256; i += 128) {
            sR4[i] = __ldg(r4 + i);
            sI4[i] = __ldg(i4 + i);
        }
    }
    __syncthreads();

    // chunk c: taps [256c, 256c+256), ascending fma (exact reference order)
    float cr = 0.0f, ci = 0.0f;
    const int base = c << 8;
    #pragma unroll 2
    for (int tt = 0; tt < 256; tt += 8) {
        float xv[8], br_[8], bi_[8];
        #pragma unroll
        for (int u = 0; u < 8; u++) {
            const int n = base + tt + u;
            const int o = (n < 512) ? (512 - n) : (n - 512);
            xv[u]  = __ldg(&g_xt0[o * 32 + b]);
            br_[u] = sbR[n];
            bi_[u] = sbI[n];
        }
        #pragma unroll
        for (int u = 0; u < 8; u++) {
            cr = fmaf(xv[u], br_[u], cr);
            ci = fmaf(xv[u], bi_[u], ci);
        }
    }
    scr[(c * 32 + b) * 2 + 0] = cr;
    scr[(c * 32 + b) * 2 + 1] = ci;
    __syncthreads();

    if (c == 0) {
        float R = scr[b * 2 + 0];
        float I = scr[b * 2 + 1];
        #pragma unroll
        for (int cc = 1; cc < 4; cc++) {            // ((c0+c1)+c2)+c3
            R = __fadd_rn(R, scr[(cc * 32 + b) * 2 + 0]);
            I = __fadd_rn(I, scr[(cc * 32 + b) * 2 + 1]);
        }
        const size_t plane = (size_t)CUTOFF * N_FRAMES;
        const size_t off = (size_t)b * plane + (size_t)k * N_FRAMES;   // t = 0
        out[off]                      = sqrtf(R * R + I * I);
        out[off + (size_t)32 * plane] = fast_atan2f(I, R);
    }
}

extern "C" void kernel_launch(void* const* d_in, const int* in_sizes, int n_in,
                              void* d_out, int out_size)
{
    const float* x     = (const float*)d_in[0];   // input_data (32, 262144)
    const float* basis = (const float*)d_in[1];   // forward_basis (1026, 1024)
    float* out = (float*)d_out;

    cudaFuncSetAttribute(stft_fft_kernel,
                         cudaFuncAttributeMaxDynamicSharedMemorySize,
                         SMEM_F * (int)sizeof(float));

    stft_prep_kernel<<<(513 * 32 + 255) / 256, 256>>>(x);

    dim3 grid((N_FRAMES + FPB - 1) / FPB, 32);
    stft_fft_kernel<<<grid, NT, SMEM_F * sizeof(float)>>>(x, basis, out);
    stft_t0_patch_kernel<<<CUTOFF, 128>>>(basis, out);
}

// round 16
// speedup vs baseline: 1.5560x; 1.5560x over previous
#include <cuda_runtime.h>
#include <math.h>

// STFT via real FFT: even/odd pack -> 512-pt radix-8 register Stockham FFT
// (3 stages, first fused with global load) -> real-split recombination.
// Exactness vs fp32 conv reference:
//  * Nyquist (k=512): Re from windowed data (basis row 512 == +-win exactly),
//    Im from the actual basis row 1025 dot (order-independent sign).
//  * Frame t=0 (even-symmetric): patch kernel replicates the reference's
//    split-K=4 order: 4 ascending-fma chunks of 256, sequential combine.
// R16: revert R15's write-out (uncoalesced 8x store wavefronts -> R14's
// segment-coalesced scheme); keep interior fast-path + sqrt.approx + poly
// atan2. Phase-determining float arithmetic bit-identical to R12..R15.

#define L_SIG    262144
#define HOP      256
#define N_FRAMES 1025
#define CUTOFF   513
#define FPB      8
#define NT       512

// smem float offsets (main kernel) -- g_tab maps 1:1 onto sm[0..3074)
#define OFF_WINC 0        // float2[512]  (win[2m], win[2m+1])
#define OFF_TW   1024     // float2[512]  exp(-2pi i m/512)
#define OFF_W1K  2048     // float2[513]  exp(-pi i k/512)
#define OFF_FBUF 3074     // 8 groups * 576 float2 (512 + pad)
#define OFF_SMAG 12290    // 513*10 (stride 10)
#define OFF_SPH  17420    // 513*10
#define OFF_NYS  22550    // 32
#define SMEM_F   22582    // 90328 bytes (2 CTAs/SM)

#define PADI(i) ((i) + ((i) >> 3))

__device__ float g_tab[3074];      // winc | tw | w1k (float pairs)
__device__ float g_xt0[513 * 32];  // t=0 frame samples, transposed [o][b]

__device__ __forceinline__ float2 cadd(float2 a, float2 b){ return make_float2(a.x+b.x, a.y+b.y); }
__device__ __forceinline__ float2 csub(float2 a, float2 b){ return make_float2(a.x-b.x, a.y-b.y); }
__device__ __forceinline__ float2 cmul(float2 a, float2 b){
    return make_float2(a.x*b.x - a.y*b.y, a.x*b.y + a.y*b.x);
}

__device__ __forceinline__ float sqrt_approx(float h)
{
    float r;
    asm("sqrt.approx.f32 %0, %1;" : "=f"(r) : "f"(h));
    return r;
}

// fast atan2: minimax atan on [0,1] (max err ~2e-7 rad), full quadrant logic.
// Sign comes from copysign(., y) -> cannot flip any phase sign vs atan2f.
__device__ __forceinline__ float fast_atan2f(float y, float x)
{
    float ax = fabsf(x), ay = fabsf(y);
    float mx = fmaxf(ax, ay), mn = fminf(ax, ay);
    float r = (mx == 0.0f) ? 0.0f : __fdividef(mn, mx);
    float t = r * r;
    float p =          -0.01172120f;
    p = fmaf(p, t,      0.05265332f);
    p = fmaf(p, t,     -0.11643287f);
    p = fmaf(p, t,      0.19354346f);
    p = fmaf(p, t,     -0.33262347f);
    p = fmaf(p, t,      0.99997726f);
    float a = p * r;
    a = (ay > ax) ? (1.5707963267948966f - a) : a;
    a = (x < 0.0f) ? (3.1415926535897932f - a) : a;
    return copysignf(a, y);
}

// 8-point DFT, natural-order in/out (verified on impulse).
__device__ __forceinline__ void fft8(float2* v)
{
    const float C = 0.70710678118654752440f;
    float2 a0=cadd(v[0],v[4]), a1=csub(v[0],v[4]);
    float2 a2=cadd(v[1],v[5]), a3=csub(v[1],v[5]);
    float2 a4=cadd(v[2],v[6]), a5=csub(v[2],v[6]);
    float2 a6=cadd(v[3],v[7]), a7=csub(v[3],v[7]);
    float2 b0=cadd(a0,a4), b2=csub(a0,a4);
    float2 w5=make_float2(a5.y,-a5.x);
    float2 b1=cadd(a1,w5), b3=csub(a1,w5);
    float2 b4=cadd(a2,a6), b6=csub(a2,a6);
    float2 w7=make_float2(a7.y,-a7.x);
    float2 b5=cadd(a3,w7), b7=csub(a3,w7);
    v[0]=cadd(b0,b4); v[4]=csub(b0,b4);
    float2 t5=make_float2(C*(b5.x+b5.y), C*(b5.y-b5.x));
    v[1]=cadd(b1,t5); v[5]=csub(b1,t5);
    float2 t6=make_float2(b6.y,-b6.x);
    v[2]=cadd(b2,t6); v[6]=csub(b2,t6);
    float2 t7=make_float2(C*(b7.y-b7.x), -C*(b7.x+b7.y));
    v[3]=cadd(b3,t7); v[7]=csub(b3,t7);
}

// ---------------------------------------------------------------------------
// Prep: tables (bit-identical sincosf expressions) + transposed x t=0 frame.
// ---------------------------------------------------------------------------
__global__ void stft_prep_kernel(const float* __restrict__ x)
{
    const int i = blockIdx.x * blockDim.x + threadIdx.x;
    if (i < 512) {
        float w0 = 0.5f - 0.5f * cosf((float)(M_PI / 512.0) * (float)(2 * i));
        float w1 = 0.5f - 0.5f * cosf((float)(M_PI / 512.0) * (float)(2 * i + 1));
        g_tab[2 * i]     = w0;
        g_tab[2 * i + 1] = w1;
        float s, c;
        sincosf((float)(-2.0 * M_PI / 512.0) * (float)i, &s, &c);
        g_tab[1024 + 2 * i]     = c;
        g_tab[1024 + 2 * i + 1] = s;
    }
    if (i < 513) {
        float s, c;
        sincosf((float)(-M_PI / 512.0) * (float)i, &s, &c);
        g_tab[2048 + 2 * i]     = c;
        g_tab[2048 + 2 * i + 1] = s;
    }
    if (i < 513 * 32) {
        const int o = i >> 5, b = i & 31;
        g_xt0[i] = x[(size_t)b * L_SIG + o];
    }
}

__global__ __launch_bounds__(NT)
void stft_fft_kernel(const float* __restrict__ x,
                     const float* __restrict__ basis,
                     float* __restrict__ out)
{
    extern __shared__ float sm[];
    float2* winc = (float2*)(sm + OFF_WINC);
    float2* tw   = (float2*)(sm + OFF_TW);
    float2* w1k  = (float2*)(sm + OFF_W1K);
    float*  smag = sm + OFF_SMAG;
    float*  sph  = sm + OFF_SPH;
    float*  nys  = sm + OFF_NYS;

    const int tid = threadIdx.x;
    const int g   = tid >> 6;          // frame group 0..7
    const int j   = tid & 63;          // lane within group
    const int b   = blockIdx.y;
    const int t0  = blockIdx.x * FPB;
    const int nf  = min(FPB, N_FRAMES - t0);
    float2* fbuf = (float2*)(sm + OFF_FBUF) + g * 576;

    // ---- tables: copy from precomputed scratch (bit-identical values) ----
    {
        const float2* gt2 = (const float2*)g_tab;
        float2* sm2 = (float2*)sm;
        for (int i = tid; i < 1537; i += NT) sm2[i] = __ldg(gt2 + i);
    }

    // preload Nyquist imag basis taps (row 1025), 8 float2 per thread
    const float2* bIm2 = (const float2*)(basis + 1025 * 1024);
    float2 bImr[8];
    #pragma unroll
    for (int r = 0; r < 8; r++) bImr[r] = __ldg(bIm2 + (j + 64 * r));

    const float* xb = x + (size_t)b * L_SIG;
    const bool interior = (blockIdx.x >= 1) && (blockIdx.x <= 126);
    __syncthreads();

    {
        const int fi  = g;
        const bool act = (fi < nf);
        const int t  = t0 + fi;
        const int s0 = t * HOP - 512;

        float2 v[8];
        float nyr = 0.f, nyi = 0.f;
        if (act) {
            if (interior) {
                // fast path: no reflect possible, straight float2 loads
                #pragma unroll
                for (int r = 0; r < 8; r++) {
                    const int m = j + 64 * r;
                    float2 xv = *(const float2*)(xb + (s0 + 2 * m));
                    float2 wn = winc[m];
                    v[r] = make_float2(xv.x * wn.x, xv.y * wn.y);
                    nyr += v[r].x - v[r].y;
                    nyi = fmaf(xv.x, bImr[r].x, fmaf(xv.y, bImr[r].y, nyi));
                }
            } else {
                #pragma unroll
                for (int r = 0; r < 8; r++) {
                    const int m  = j + 64 * r;
                    const int o0 = s0 + 2 * m;
                    float xa, xc;
                    if (o0 >= 0 && o0 < L_SIG - 1) {
                        float2 xv = *(const float2*)(xb + o0);
                        xa = xv.x; xc = xv.y;
                    } else {
                        int p0 = (o0 < 0) ? -o0 : ((o0 >= L_SIG) ? 2 * L_SIG - 2 - o0 : o0);
                        int o1 = o0 + 1;
                        int p1 = (o1 < 0) ? -o1 : ((o1 >= L_SIG) ? 2 * L_SIG - 2 - o1 : o1);
                        xa = xb[p0]; xc = xb[p1];
                    }
                    float2 wn = winc[m];
                    v[r] = make_float2(xa * wn.x, xc * wn.y);
                    nyr += v[r].x - v[r].y;                   // row512 = (-1)^n * win
                    nyi = fmaf(xa, bImr[r].x, fmaf(xc, bImr[r].y, nyi));
                }
            }
            #pragma unroll
            for (int off = 16; off; off >>= 1) {
                nyr += __shfl_xor_sync(0xFFFFFFFFu, nyr, off);
                nyi += __shfl_xor_sync(0xFFFFFFFFu, nyi, off);
            }
            fft8(v);                                          // stage 1 (Ns=1)
        }
        __syncthreads();
        if (act) {
            if ((tid & 31) == 0) {
                nys[g * 4 + (j >> 5) * 2 + 0] = nyr;
                nys[g * 4 + (j >> 5) * 2 + 1] = nyi;
            }
            #pragma unroll
            for (int r = 0; r < 8; r++) fbuf[PADI(8 * j + r)] = v[r];
        }
        __syncthreads();
        // stage 2 (Ns=8)
        if (act) {
            #pragma unroll
            for (int r = 0; r < 8; r++) v[r] = fbuf[PADI(j + 64 * r)];
            const int rr = (j & 7) * 8;
            #pragma unroll
            for (int r = 1; r < 8; r++) v[r] = cmul(v[r], tw[r * rr]);
            fft8(v);
        }
        __syncthreads();
        if (act) {
            const int idxD = ((j >> 3) << 6) + (j & 7);
            #pragma unroll
            for (int r = 0; r < 8; r++) fbuf[PADI(idxD + (r << 3))] = v[r];
        }
        __syncthreads();
        // stage 3 (Ns=64)
        if (act) {
            #pragma unroll
            for (int r = 0; r < 8; r++) v[r] = fbuf[PADI(j + 64 * r)];
            #pragma unroll
            for (int r = 1; r < 8; r++) v[r] = cmul(v[r], tw[r * j]);
            fft8(v);
        }
        __syncthreads();
        if (act) {
            #pragma unroll
            for (int r = 0; r < 8; r++) fbuf[PADI(j + 64 * r)] = v[r];
        }
        __syncthreads();
        // ---- real-split recombination + mag/phase ----
        if (act) {
            #pragma unroll
            for (int it = 0; it < 9; it++) {
                const int k = j + (it << 6);
                if (k < CUTOFF) {
                    float2 zk = (k < 512) ? fbuf[PADI(k)] : fbuf[0];
                    float2 zm = fbuf[PADI((512 - k) & 511)];
                    float Er = 0.5f * (zk.x + zm.x);
                    float Ei = 0.5f * (zk.y - zm.y);
                    float Or = 0.5f * (zk.y + zm.y);
                    float Oi = -0.5f * (zk.x - zm.x);
                    float2 w = w1k[k];
                    float Xr = Er + w.x * Or - w.y * Oi;
                    float Xi = Ei + w.x * Oi + w.y * Or;
                    if (k == 512) {
                        Xr = nys[g * 4 + 0] + nys[g * 4 + 2];
                        Xi = nys[g * 4 + 1] + nys[g * 4 + 3];
                    }
                    smag[k * 10 + fi] = sqrt_approx(fmaf(Xr, Xr, Xi * Xi));
                    sph [k * 10 + fi] = fast_atan2f(Xi, Xr);
                }
            }
        }
    }
    __syncthreads();

    // ---- write-out: R14 scheme -- 8 consecutive lanes fill one 32B row
    // segment per STG instruction (4 sectors/warp-instr, coalesced) ----
    const size_t plane = (size_t)CUTOFF * N_FRAMES;
    float* omag = out + (size_t)b * plane;
    float* oph  = out + (size_t)32 * plane + (size_t)b * plane;
    const int tot = CUTOFF * nf;
    for (int e = tid; e < tot; e += NT) {
        int k, f;
        if (nf == FPB) { k = e >> 3; f = e & 7; }
        else           { k = e / nf; f = e % nf; }
        size_t off = (size_t)k * N_FRAMES + (size_t)(t0 + f);
        omag[off] = smag[k * 10 + f];
        oph [off] = sph [k * 10 + f];
    }
}

// ---------------------------------------------------------------------------
// t=0 column patch, reference split-K=4 order (decoded R8/R9):
// block per k (513 blocks), 128 threads = 4 chunks x 32 batches.
// xv from transposed GMEM scratch (coalesced, L1/L2-resident); basis rows in
// smem (broadcast). 8-tap register tiles preserve the exact ascending order.
// ---------------------------------------------------------------------------
__global__ __launch_bounds__(128)
void stft_t0_patch_kernel(const float* __restrict__ basis,
                          float* __restrict__ out)
{
    __shared__ float sbR[1024];
    __shared__ float sbI[1024];
    __shared__ float scr[256];

    const int k   = blockIdx.x;          // 0..512
    const int tid = threadIdx.x;
    const int c   = tid >> 5;            // chunk 0..3
    const int b   = tid & 31;            // batch

    {
        const float4* r4 = (const float4*)(basis + (size_t)k * 1024);
        const float4* i4 = (const float4*)(basis + (size_t)(513 + k) * 1024);
        float4* sR4 = (float4*)sbR;
        float4* sI4 = (float4*)sbI;
        for (int i = tid; i < 256; i += 128) {
            sR4[i] = __ldg(r4 + i);
            sI4[i] = __ldg(i4 + i);
        }
    }
    __syncthreads();

    // chunk c: taps [256c, 256c+256), ascending fma (exact reference order)
    float cr = 0.0f, ci = 0.0f;
    const int base = c << 8;
    #pragma unroll 2
    for (int tt = 0; tt < 256; tt += 8) {
        float xv[8], br_[8], bi_[8];
        #pragma unroll
        for (int u = 0; u < 8; u++) {
            const int n = base + tt + u;
            const int o = (n < 512) ? (512 - n) : (n - 512);
            xv[u]  = __ldg(&g_xt0[o * 32 + b]);
            br_[u] = sbR[n];
            bi_[u] = sbI[n];
        }
        #pragma unroll
        for (int u = 0; u < 8; u++) {
            cr = fmaf(xv[u], br_[u], cr);
            ci = fmaf(xv[u], bi_[u], ci);
        }
    }
    scr[(c * 32 + b) * 2 + 0] = cr;
    scr[(c * 32 + b) * 2 + 1] = ci;
    __syncthreads();

    if (c == 0) {
        float R = scr[b * 2 + 0];
        float I = scr[b * 2 + 1];
        #pragma unroll
        for (int cc = 1; cc < 4; cc++) {            // ((c0+c1)+c2)+c3
            R = __fadd_rn(R, scr[(cc * 32 + b) * 2 + 0]);
            I = __fadd_rn(I, scr[(cc * 32 + b) * 2 + 1]);
        }
        const size_t plane = (size_t)CUTOFF * N_FRAMES;
        const size_t off = (size_t)b * plane + (size_t)k * N_FRAMES;   // t = 0
        out[off]                      = sqrtf(R * R + I * I);
        out[off + (size_t)32 * plane] = fast_atan2f(I, R);
    }
}

extern "C" void kernel_launch(void* const* d_in, const int* in_sizes, int n_in,
                              void* d_out, int out_size)
{
    const float* x     = (const float*)d_in[0];   // input_data (32, 262144)
    const float* basis = (const float*)d_in[1];   // forward_basis (1026, 1024)
    float* out = (float*)d_out;

    cudaFuncSetAttribute(stft_fft_kernel,
                         cudaFuncAttributeMaxDynamicSharedMemorySize,
                         SMEM_F * (int)sizeof(float));

    stft_prep_kernel<<<(513 * 32 + 255) / 256, 256>>>(x);

    dim3 grid((N_FRAMES + FPB - 1) / FPB, 32);
    stft_fft_kernel<<<grid, NT, SMEM_F * sizeof(float)>>>(x, basis, out);
    stft_t0_patch_kernel<<<CUTOFF, 128>>>(basis, out);
}

// round 17
// speedup vs baseline: 1.7095x; 1.0986x over previous
#include <cuda_runtime.h>
#include <math.h>

// STFT via real FFT: even/odd pack -> 512-pt radix-8 register Stockham FFT
// (3 stages, first fused with global load) -> real-split recombination.
// Exactness vs fp32 conv reference:
//  * Nyquist (k=512): Re from windowed data (basis row 512 == +-win exactly),
//    Im from the actual basis row 1025 dot (order-independent sign).
//  * Frame t=0 (even-symmetric): patch kernel replicates the reference's
//    split-K=4 order: 4 ascending-fma chunks of 256, sequential combine.
// R17: fused recomb+store -- mag/phase computed directly in the coalesced
// (k = e>>3, f = e&7) store order, reading spectra straight from the other
// groups' fbuf (group stride 577 float2 for bank spread). Removes the 41KB
// smag/sph staging, its STS/LDS round-trip, and one barrier.
// Per-(k,frame) float expressions bit-identical to R12..R16.

#define L_SIG    262144
#define HOP      256
#define N_FRAMES 1025
#define CUTOFF   513
#define FPB      8
#define NT       512

// smem float offsets (main kernel) -- g_tab maps 1:1 onto sm[0..3074)
#define OFF_WINC 0        // float2[512]  (win[2m], win[2m+1])
#define OFF_TW   1024     // float2[512]  exp(-2pi i m/512)
#define OFF_W1K  2048     // float2[513]  exp(-pi i k/512)
#define OFF_FBUF 3074     // 8 groups * 577 float2 (512 + pad + bank offset)
#define OFF_NYS  12306    // 32
#define SMEM_F   12338    // 49352 bytes

#define PADI(i) ((i) + ((i) >> 3))
#define GSTRIDE 577       // float2 per group buffer

__device__ float g_tab[3074];      // winc | tw | w1k (float pairs)
__device__ float g_xt0[513 * 32];  // t=0 frame samples, transposed [o][b]

__device__ __forceinline__ float2 cadd(float2 a, float2 b){ return make_float2(a.x+b.x, a.y+b.y); }
__device__ __forceinline__ float2 csub(float2 a, float2 b){ return make_float2(a.x-b.x, a.y-b.y); }
__device__ __forceinline__ float2 cmul(float2 a, float2 b){
    return make_float2(a.x*b.x - a.y*b.y, a.x*b.y + a.y*b.x);
}

__device__ __forceinline__ float sqrt_approx(float h)
{
    float r;
    asm("sqrt.approx.f32 %0, %1;" : "=f"(r) : "f"(h));
    return r;
}

// fast atan2: minimax atan on [0,1] (max err ~2e-7 rad), full quadrant logic.
// Sign comes from copysign(., y) -> cannot flip any phase sign vs atan2f.
__device__ __forceinline__ float fast_atan2f(float y, float x)
{
    float ax = fabsf(x), ay = fabsf(y);
    float mx = fmaxf(ax, ay), mn = fminf(ax, ay);
    float r = (mx == 0.0f) ? 0.0f : __fdividef(mn, mx);
    float t = r * r;
    float p =          -0.01172120f;
    p = fmaf(p, t,      0.05265332f);
    p = fmaf(p, t,     -0.11643287f);
    p = fmaf(p, t,      0.19354346f);
    p = fmaf(p, t,     -0.33262347f);
    p = fmaf(p, t,      0.99997726f);
    float a = p * r;
    a = (ay > ax) ? (1.5707963267948966f - a) : a;
    a = (x < 0.0f) ? (3.1415926535897932f - a) : a;
    return copysignf(a, y);
}

// 8-point DFT, natural-order in/out (verified on impulse).
__device__ __forceinline__ void fft8(float2* v)
{
    const float C = 0.70710678118654752440f;
    float2 a0=cadd(v[0],v[4]), a1=csub(v[0],v[4]);
    float2 a2=cadd(v[1],v[5]), a3=csub(v[1],v[5]);
    float2 a4=cadd(v[2],v[6]), a5=csub(v[2],v[6]);
    float2 a6=cadd(v[3],v[7]), a7=csub(v[3],v[7]);
    float2 b0=cadd(a0,a4), b2=csub(a0,a4);
    float2 w5=make_float2(a5.y,-a5.x);
    float2 b1=cadd(a1,w5), b3=csub(a1,w5);
    float2 b4=cadd(a2,a6), b6=csub(a2,a6);
    float2 w7=make_float2(a7.y,-a7.x);
    float2 b5=cadd(a3,w7), b7=csub(a3,w7);
    v[0]=cadd(b0,b4); v[4]=csub(b0,b4);
    float2 t5=make_float2(C*(b5.x+b5.y), C*(b5.y-b5.x));
    v[1]=cadd(b1,t5); v[5]=csub(b1,t5);
    float2 t6=make_float2(b6.y,-b6.x);
    v[2]=cadd(b2,t6); v[6]=csub(b2,t6);
    float2 t7=make_float2(C*(b7.y-b7.x), -C*(b7.x+b7.y));
    v[3]=cadd(b3,t7); v[7]=csub(b3,t7);
}

// ---------------------------------------------------------------------------
// Prep: tables (bit-identical sincosf expressions) + transposed x t=0 frame.
// ---------------------------------------------------------------------------
__global__ void stft_prep_kernel(const float* __restrict__ x)
{
    const int i = blockIdx.x * blockDim.x + threadIdx.x;
    if (i < 512) {
        float w0 = 0.5f - 0.5f * cosf((float)(M_PI / 512.0) * (float)(2 * i));
        float w1 = 0.5f - 0.5f * cosf((float)(M_PI / 512.0) * (float)(2 * i + 1));
        g_tab[2 * i]     = w0;
        g_tab[2 * i + 1] = w1;
        float s, c;
        sincosf((float)(-2.0 * M_PI / 512.0) * (float)i, &s, &c);
        g_tab[1024 + 2 * i]     = c;
        g_tab[1024 + 2 * i + 1] = s;
    }
    if (i < 513) {
        float s, c;
        sincosf((float)(-M_PI / 512.0) * (float)i, &s, &c);
        g_tab[2048 + 2 * i]     = c;
        g_tab[2048 + 2 * i + 1] = s;
    }
    if (i < 513 * 32) {
        const int o = i >> 5, b = i & 31;
        g_xt0[i] = x[(size_t)b * L_SIG + o];
    }
}

__global__ __launch_bounds__(NT)
void stft_fft_kernel(const float* __restrict__ x,
                     const float* __restrict__ basis,
                     float* __restrict__ out)
{
    extern __shared__ float sm[];
    float2* winc = (float2*)(sm + OFF_WINC);
    float2* tw   = (float2*)(sm + OFF_TW);
    float2* w1k  = (float2*)(sm + OFF_W1K);
    float2* fbA  = (float2*)(sm + OFF_FBUF);
    float*  nys  = sm + OFF_NYS;

    const int tid = threadIdx.x;
    const int g   = tid >> 6;          // frame group 0..7
    const int j   = tid & 63;          // lane within group
    const int b   = blockIdx.y;
    const int t0  = blockIdx.x * FPB;
    const int nf  = min(FPB, N_FRAMES - t0);
    float2* fbuf = fbA + g * GSTRIDE;

    // ---- tables: copy from precomputed scratch (bit-identical values) ----
    {
        const float2* gt2 = (const float2*)g_tab;
        float2* sm2 = (float2*)sm;
        for (int i = tid; i < 1537; i += NT) sm2[i] = __ldg(gt2 + i);
    }

    // preload Nyquist imag basis taps (row 1025), 8 float2 per thread
    const float2* bIm2 = (const float2*)(basis + 1025 * 1024);
    float2 bImr[8];
    #pragma unroll
    for (int r = 0; r < 8; r++) bImr[r] = __ldg(bIm2 + (j + 64 * r));

    const float* xb = x + (size_t)b * L_SIG;
    const bool interior = (blockIdx.x >= 1) && (blockIdx.x <= 126);
    __syncthreads();

    {
        const int fi  = g;
        const bool act = (fi < nf);
        const int t  = t0 + fi;
        const int s0 = t * HOP - 512;

        float2 v[8];
        float nyr = 0.f, nyi = 0.f;
        if (act) {
            if (interior) {
                // fast path: no reflect possible, straight float2 loads
                #pragma unroll
                for (int r = 0; r < 8; r++) {
                    const int m = j + 64 * r;
                    float2 xv = *(const float2*)(xb + (s0 + 2 * m));
                    float2 wn = winc[m];
                    v[r] = make_float2(xv.x * wn.x, xv.y * wn.y);
                    nyr += v[r].x - v[r].y;
                    nyi = fmaf(xv.x, bImr[r].x, fmaf(xv.y, bImr[r].y, nyi));
                }
            } else {
                #pragma unroll
                for (int r = 0; r < 8; r++) {
                    const int m  = j + 64 * r;
                    const int o0 = s0 + 2 * m;
                    float xa, xc;
                    if (o0 >= 0 && o0 < L_SIG - 1) {
                        float2 xv = *(const float2*)(xb + o0);
                        xa = xv.x; xc = xv.y;
                    } else {
                        int p0 = (o0 < 0) ? -o0 : ((o0 >= L_SIG) ? 2 * L_SIG - 2 - o0 : o0);
                        int o1 = o0 + 1;
                        int p1 = (o1 < 0) ? -o1 : ((o1 >= L_SIG) ? 2 * L_SIG - 2 - o1 : o1);
                        xa = xb[p0]; xc = xb[p1];
                    }
                    float2 wn = winc[m];
                    v[r] = make_float2(xa * wn.x, xc * wn.y);
                    nyr += v[r].x - v[r].y;                   // row512 = (-1)^n * win
                    nyi = fmaf(xa, bImr[r].x, fmaf(xc, bImr[r].y, nyi));
                }
            }
            #pragma unroll
            for (int off = 16; off; off >>= 1) {
                nyr += __shfl_xor_sync(0xFFFFFFFFu, nyr, off);
                nyi += __shfl_xor_sync(0xFFFFFFFFu, nyi, off);
            }
            fft8(v);                                          // stage 1 (Ns=1)
        }
        __syncthreads();
        if (act) {
            if ((tid & 31) == 0) {
                nys[g * 4 + (j >> 5) * 2 + 0] = nyr;
                nys[g * 4 + (j >> 5) * 2 + 1] = nyi;
            }
            #pragma unroll
            for (int r = 0; r < 8; r++) fbuf[PADI(8 * j + r)] = v[r];
        }
        __syncthreads();
        // stage 2 (Ns=8)
        if (act) {
            #pragma unroll
            for (int r = 0; r < 8; r++) v[r] = fbuf[PADI(j + 64 * r)];
            const int rr = (j & 7) * 8;
            #pragma unroll
            for (int r = 1; r < 8; r++) v[r] = cmul(v[r], tw[r * rr]);
            fft8(v);
        }
        __syncthreads();
        if (act) {
            const int idxD = ((j >> 3) << 6) + (j & 7);
            #pragma unroll
            for (int r = 0; r < 8; r++) fbuf[PADI(idxD + (r << 3))] = v[r];
        }
        __syncthreads();
        // stage 3 (Ns=64)
        if (act) {
            #pragma unroll
            for (int r = 0; r < 8; r++) v[r] = fbuf[PADI(j + 64 * r)];
            #pragma unroll
            for (int r = 1; r < 8; r++) v[r] = cmul(v[r], tw[r * j]);
            fft8(v);
        }
        __syncthreads();
        if (act) {
            #pragma unroll
            for (int r = 0; r < 8; r++) fbuf[PADI(j + 64 * r)] = v[r];
        }
        __syncthreads();
    }

    // ---- fused recomb + mag/phase + coalesced store ----
    // thread e: k = e>>3 (or e/nf), f = e&7 -- reads group f's spectrum
    // directly; store pattern identical to the R14/R16 coalesced scheme.
    const size_t plane = (size_t)CUTOFF * N_FRAMES;
    float* omag = out + (size_t)b * plane;
    float* oph  = out + (size_t)32 * plane + (size_t)b * plane;
    const int tot = CUTOFF * nf;
    for (int e = tid; e < tot; e += NT) {
        int k, f;
        if (nf == FPB) { k = e >> 3; f = e & 7; }
        else           { k = e / nf; f = e % nf; }
        const float2* fb = fbA + f * GSTRIDE;
        float2 zk = (k < 512) ? fb[PADI(k)] : fb[0];
        float2 zm = fb[PADI((512 - k) & 511)];
        float Er = 0.5f * (zk.x + zm.x);
        float Ei = 0.5f * (zk.y - zm.y);
        float Or = 0.5f * (zk.y + zm.y);
        float Oi = -0.5f * (zk.x - zm.x);
        float2 w = w1k[k];
        float Xr = Er + w.x * Or - w.y * Oi;
        float Xi = Ei + w.x * Oi + w.y * Or;
        if (k == 512) {
            Xr = nys[f * 4 + 0] + nys[f * 4 + 2];
            Xi = nys[f * 4 + 1] + nys[f * 4 + 3];
        }
        size_t off = (size_t)k * N_FRAMES + (size_t)(t0 + f);
        omag[off] = sqrt_approx(fmaf(Xr, Xr, Xi * Xi));
        oph [off] = fast_atan2f(Xi, Xr);
    }
}

// ---------------------------------------------------------------------------
// t=0 column patch, reference split-K=4 order (decoded R8/R9):
// block per k (513 blocks), 128 threads = 4 chunks x 32 batches.
// xv from transposed GMEM scratch (coalesced, L1/L2-resident); basis rows in
// smem (broadcast). 8-tap register tiles preserve the exact ascending order.
// ---------------------------------------------------------------------------
__global__ __launch_bounds__(128)
void stft_t0_patch_kernel(const float* __restrict__ basis,
                          float* __restrict__ out)
{
    __shared__ float sbR[1024];
    __shared__ float sbI[1024];
    __shared__ float scr[256];

    const int k   = blockIdx.x;          // 0..512
    const int tid = threadIdx.x;
    const int c   = tid >> 5;            // chunk 0..3
    const int b   = tid & 31;            // batch

    {
        const float4* r4 = (const float4*)(basis + (size_t)k * 1024);
        const float4* i4 = (const float4*)(basis + (size_t)(513 + k) * 1024);
        float4* sR4 = (float4*)sbR;
        float4* sI4 = (float4*)sbI;
        for (int i = tid; i < 256; i += 128) {
            sR4[i] = __ldg(r4 + i);
            sI4[i] = __ldg(i4 + i);
        }
    }
    __syncthreads();

    // chunk c: taps [256c, 256c+256), ascending fma (exact reference order)
    float cr = 0.0f, ci = 0.0f;
    const int base = c << 8;
    #pragma unroll 2
    for (int tt = 0; tt < 256; tt += 8) {
        float xv[8], br_[8], bi_[8];
        #pragma unroll
        for (int u = 0; u < 8; u++) {
            const int n = base + tt + u;
            const int o = (n < 512) ? (512 - n) : (n - 512);
            xv[u]  = __ldg(&g_xt0[o * 32 + b]);
            br_[u] = sbR[n];
            bi_[u] = sbI[n];
        }
        #pragma unroll
        for (int u = 0; u < 8; u++) {
            cr = fmaf(xv[u], br_[u], cr);
            ci = fmaf(xv[u], bi_[u], ci);
        }
    }
    scr[(c * 32 + b) * 2 + 0] = cr;
    scr[(c * 32 + b) * 2 + 1] = ci;
    __syncthreads();

    if (c == 0) {
        float R = scr[b * 2 + 0];
        float I = scr[b * 2 + 1];
        #pragma unroll
        for (int cc = 1; cc < 4; cc++) {            // ((c0+c1)+c2)+c3
            R = __fadd_rn(R, scr[(cc * 32 + b) * 2 + 0]);
            I = __fadd_rn(I, scr[(cc * 32 + b) * 2 + 1]);
        }
        const size_t plane = (size_t)CUTOFF * N_FRAMES;
        const size_t off = (size_t)b * plane + (size_t)k * N_FRAMES;   // t = 0
        out[off]                      = sqrtf(R * R + I * I);
        out[off + (size_t)32 * plane] = fast_atan2f(I, R);
    }
}

extern "C" void kernel_launch(void* const* d_in, const int* in_sizes, int n_in,
                              void* d_out, int out_size)
{
    const float* x     = (const float*)d_in[0];   // input_data (32, 262144)
    const float* basis = (const float*)d_in[1];   // forward_basis (1026, 1024)
    float* out = (float*)d_out;

    cudaFuncSetAttribute(stft_fft_kernel,
                         cudaFuncAttributeMaxDynamicSharedMemorySize,
                         SMEM_F * (int)sizeof(float));

    stft_prep_kernel<<<(513 * 32 + 255) / 256, 256>>>(x);

    dim3 grid((N_FRAMES + FPB - 1) / FPB, 32);
    stft_fft_kernel<<<grid, NT, SMEM_F * sizeof(float)>>>(x, basis, out);
    stft_t0_patch_kernel<<<CUTOFF, 128>>>(basis, out);
}